// round 1
// baseline (speedup 1.0000x reference)
#include <cuda_runtime.h>

// Problem constants (from reference)
#define BB 16
#define HH 768
#define WW 1280
#define PAD 4

// dist = exp(-(pad^2+pad^2)/(2*sigma_g^2)) = exp(-32/18)
// precomputed on host side as constant
__device__ __forceinline__ float4 ld4(const float* p) {
    return *reinterpret_cast<const float4*>(p);
}

__global__ __launch_bounds__(256) void bilateral_kernel(
    const float* __restrict__ img,
    const float* __restrict__ est,
    float* __restrict__ out)
{
    // Each thread handles one float4 (4 consecutive x).
    const int W4 = WW / 4;                       // 320
    const long long tid = (long long)blockIdx.x * blockDim.x + threadIdx.x;
    const long long total = (long long)BB * HH * W4;
    if (tid >= total) return;

    const int x4 = (int)(tid % W4);
    const int yb = (int)(tid / W4);
    const int y  = yb % HH;
    const int b  = yb / HH;

    const int x = x4 * 4;

    const float* imgB = img + (long long)b * HH * WW;
    const float* estB = est + (long long)b * HH * WW;
    float*       outB = out + (long long)b * HH * WW;

    // center image values
    const float4 c = ld4(imgB + (long long)y * WW + x);

    // shifted image: img[y+4, x+4..x+7], zero if out of range.
    // x is a multiple of 4, so x+4..x+7 are all < W iff x+4+3 < W, i.e. x <= W-8.
    float4 s = make_float4(0.f, 0.f, 0.f, 0.f);
    if (y + PAD < HH && x + PAD + 3 < WW) {
        s = ld4(imgB + (long long)(y + PAD) * WW + (x + PAD));
    }

    // disp = est[y-4, x-4..x-1], zero if out of range. x-4 >= 0 iff x >= 4.
    float4 dsp = make_float4(0.f, 0.f, 0.f, 0.f);
    if (y >= PAD && x >= PAD) {
        dsp = ld4(estB + (long long)(y - PAD) * WW + (x - PAD));
    }

    const float dist = 0.16901332f;   // exp(-32/18)
    const float eps  = 1e-12f;

    float4 r;
    {
        float d = c.x - s.x;
        float w = dist * __expf(d * d * (-0.125f));
        r.x = (dsp.x * w + eps) / (w + eps);
    }
    {
        float d = c.y - s.y;
        float w = dist * __expf(d * d * (-0.125f));
        r.y = (dsp.y * w + eps) / (w + eps);
    }
    {
        float d = c.z - s.z;
        float w = dist * __expf(d * d * (-0.125f));
        r.z = (dsp.z * w + eps) / (w + eps);
    }
    {
        float d = c.w - s.w;
        float w = dist * __expf(d * d * (-0.125f));
        r.w = (dsp.w * w + eps) / (w + eps);
    }

    *reinterpret_cast<float4*>(outB + (long long)y * WW + x) = r;
}

extern "C" void kernel_launch(void* const* d_in, const int* in_sizes, int n_in,
                              void* d_out, int out_size)
{
    const float* img = (const float*)d_in[0];   // leftImage
    const float* est = (const float*)d_in[1];   // estDisp
    float* out = (float*)d_out;

    const long long total = (long long)BB * HH * (WW / 4);   // 3,932,160
    const int threads = 256;
    const int blocks = (int)((total + threads - 1) / threads);
    bilateral_kernel<<<blocks, threads>>>(img, est, out);
}

// round 2
// speedup vs baseline: 1.2403x; 1.2403x over previous
#include <cuda_runtime.h>

// Problem constants
#define BB 16
#define HH 768
#define WW 1280
#define PAD 4

// Math facts used:
//   out = (dsp*w + eps)/(w + eps) = dsp + eps*(1-dsp)/(w+eps)
//   w = exp(-32/18) * exp(-d^2/8), d in [-1,1]  =>  w in [0.1492, 0.1690]
//   => |out - dsp| <= 6.7e-12 absolute, always.
// So interior output == shifted estDisp, except where dsp ~ 0 (handled exactly
// by the slow path).

__device__ __forceinline__ float4 ld4(const float* p) {
    return *reinterpret_cast<const float4*>(p);
}

__device__ __forceinline__ float full_formula(const float* imgB, const float* estB,
                                              int y, int xi)
{
    const float dist = 0.16901332f;   // exp(-32/18)
    const float eps  = 1e-12f;
    float dsp = 0.0f;
    if (y >= PAD && xi >= PAD)
        dsp = estB[(y - PAD) * WW + (xi - PAD)];
    float c = imgB[y * WW + xi];
    float s = 0.0f;
    if (y + PAD < HH && xi + PAD < WW)
        s = imgB[(y + PAD) * WW + (xi + PAD)];
    float d = c - s;
    float w = dist * __expf(d * d * (-0.125f));
    return (dsp * w + eps) / (w + eps);
}

__global__ __launch_bounds__(256) void bilateral_kernel(
    const float* __restrict__ img,
    const float* __restrict__ est,
    float* __restrict__ out)
{
    // Each thread handles 8 consecutive x (two float4s). 1280/8 = 160 chunks/row.
    const int CPR = WW / 8;   // 160
    const int tid = blockIdx.x * blockDim.x + threadIdx.x;
    const int total = BB * HH * CPR;
    if (tid >= total) return;

    const int x8 = tid % CPR;
    const int yb = tid / CPR;
    const int y  = yb % HH;
    const int b  = yb / HH;
    const int x  = x8 * 8;

    const float* imgB = img + (long long)b * HH * WW;
    const float* estB = est + (long long)b * HH * WW;
    float*       outB = out + (long long)b * HH * WW;

    bool fast = (y >= PAD) && (x >= PAD);

    if (fast) {
        // est addresses x-4 .. x+3 : two aligned float4 loads (x multiple of 8)
        const float* src = estB + (y - PAD) * WW + (x - PAD);
        float4 d0 = ld4(src);
        float4 d1 = ld4(src + 4);

        float mn = fminf(fminf(fminf(d0.x, d0.y), fminf(d0.z, d0.w)),
                         fminf(fminf(d1.x, d1.y), fminf(d1.z, d1.w)));
        if (mn >= 1e-5f) {
            float4* dst = reinterpret_cast<float4*>(outB + y * WW + x);
            dst[0] = d0;
            dst[1] = d1;
            return;
        }
        // fall through to exact path (rare: any dsp < 1e-5)
    }

    // Exact path: boundary chunks and rare tiny-dsp chunks.
    float r[8];
#pragma unroll
    for (int i = 0; i < 8; i++)
        r[i] = full_formula(imgB, estB, y, x + i);

    float4* dst = reinterpret_cast<float4*>(outB + y * WW + x);
    dst[0] = make_float4(r[0], r[1], r[2], r[3]);
    dst[1] = make_float4(r[4], r[5], r[6], r[7]);
}

extern "C" void kernel_launch(void* const* d_in, const int* in_sizes, int n_in,
                              void* d_out, int out_size)
{
    const float* img = (const float*)d_in[0];   // leftImage
    const float* est = (const float*)d_in[1];   // estDisp
    float* out = (float*)d_out;

    const int total = BB * HH * (WW / 8);       // 1,966,080 threads
    const int threads = 256;
    const int blocks = (total + threads - 1) / threads;
    bilateral_kernel<<<blocks, threads>>>(img, est, out);
}